// round 1
// baseline (speedup 1.0000x reference)
#include <cuda_runtime.h>
#include <cuda_bf16.h>
#include <math.h>

#define N_NODES_MAX 100000
#define IN_DIM 512
#define HID 256

// Ping-pong scratch (static device arrays: allocation-free per harness rules)
__device__ float g_bufA[(size_t)N_NODES_MAX * HID];
__device__ float g_bufB[(size_t)N_NODES_MAX * HID];

// ---------------------------------------------------------------------------
// Tiled fp32 GEMM: C[M,N] = A[M,K] @ B[K,N], row-major, N multiple of 64,
// K multiple of 16. BM=64, BN=64, BK=16, 256 threads, 4x4 per thread.
// ---------------------------------------------------------------------------
__global__ __launch_bounds__(256) void gemm_kernel(
    const float* __restrict__ A, const float* __restrict__ B,
    float* __restrict__ C, int M, int K, int N)
{
    __shared__ float As[16][68];   // [k][row], padded stride 68 (16B-align ok, fewer conflicts)
    __shared__ float Bs[16][64];   // [k][col]

    const int tid = threadIdx.x;
    const int tx = tid & 15;        // 0..15 -> 4 cols each
    const int ty = tid >> 4;        // 0..15 -> 4 rows each
    const int rowBase = blockIdx.y * 64;
    const int colBase = blockIdx.x * 64;

    float acc[4][4];
#pragma unroll
    for (int i = 0; i < 4; i++)
#pragma unroll
        for (int j = 0; j < 4; j++) acc[i][j] = 0.f;

    // A loader mapping: each thread loads one float4 of A (64 rows x 16 k)
    const int aRow = tid >> 2;            // 0..63
    const int aK   = (tid & 3) * 4;       // 0,4,8,12
    // B loader mapping: each thread loads one float4 of B (16 k x 64 cols)
    const int bK   = tid >> 4;            // 0..15
    const int bCol = (tid & 15) * 4;      // 0..60

    for (int k0 = 0; k0 < K; k0 += 16) {
        float4 av = make_float4(0.f, 0.f, 0.f, 0.f);
        const int gr = rowBase + aRow;
        if (gr < M)
            av = *(const float4*)(A + (size_t)gr * K + k0 + aK);
        As[aK + 0][aRow] = av.x;
        As[aK + 1][aRow] = av.y;
        As[aK + 2][aRow] = av.z;
        As[aK + 3][aRow] = av.w;

        float4 bv = *(const float4*)(B + (size_t)(k0 + bK) * N + colBase + bCol);
        *(float4*)&Bs[bK][bCol] = bv;

        __syncthreads();

#pragma unroll
        for (int k = 0; k < 16; k++) {
            float4 a = *(const float4*)&As[k][ty * 4];
            float4 b = *(const float4*)&Bs[k][tx * 4];
            float ar[4] = {a.x, a.y, a.z, a.w};
            float br[4] = {b.x, b.y, b.z, b.w};
#pragma unroll
            for (int i = 0; i < 4; i++)
#pragma unroll
                for (int j = 0; j < 4; j++)
                    acc[i][j] = fmaf(ar[i], br[j], acc[i][j]);
        }
        __syncthreads();
    }

#pragma unroll
    for (int i = 0; i < 4; i++) {
        const int gr = rowBase + ty * 4 + i;
        if (gr < M) {
            float4 v = make_float4(acc[i][0], acc[i][1], acc[i][2], acc[i][3]);
            *(float4*)(C + (size_t)gr * N + colBase + tx * 4) = v;
        }
    }
}

// ---------------------------------------------------------------------------
// SpMM scatter: for each edge e, Hdst[rows[e], :] += vals[e] * Ssrc[cols[e], :]
// One warp per edge; 256 floats per row -> 2 float4 per lane; atomicAdd scatter.
// ---------------------------------------------------------------------------
__global__ __launch_bounds__(256) void spmm_kernel(
    const int* __restrict__ rows, const int* __restrict__ cols,
    const float* __restrict__ vals,
    const float* __restrict__ S, float* __restrict__ H, int E)
{
    const int warp = (blockIdx.x * blockDim.x + threadIdx.x) >> 5;
    const int lane = threadIdx.x & 31;
    if (warp >= E) return;

    const int   r = rows[warp];
    const int   c = cols[warp];
    const float v = vals[warp];

    const float4* __restrict__ src = (const float4*)(S + (size_t)c * HID);
    float* __restrict__ dst = H + (size_t)r * HID;

#pragma unroll
    for (int half = 0; half < 2; half++) {
        float4 s = __ldg(&src[lane + half * 32]);
        const int base = (lane + half * 32) * 4;
        atomicAdd(&dst[base + 0], s.x * v);
        atomicAdd(&dst[base + 1], s.y * v);
        atomicAdd(&dst[base + 2], s.z * v);
        atomicAdd(&dst[base + 3], s.w * v);
    }
}

// ---------------------------------------------------------------------------
// H = relu(H + b1), elementwise over N*HID, float4-vectorized
// ---------------------------------------------------------------------------
__global__ __launch_bounds__(256) void bias_relu_kernel(
    float* __restrict__ H, const float* __restrict__ b, int n4)
{
    const int i = blockIdx.x * blockDim.x + threadIdx.x;
    if (i >= n4) return;
    const int col4 = i & (HID / 4 - 1);     // which float4 within the 256-wide row
    float4 h = ((float4*)H)[i];
    float4 bb = ((const float4*)b)[col4];
    h.x = fmaxf(h.x + bb.x, 0.f);
    h.y = fmaxf(h.y + bb.y, 0.f);
    h.z = fmaxf(h.z + bb.z, 0.f);
    h.w = fmaxf(h.w + bb.w, 0.f);
    ((float4*)H)[i] = h;
}

// ---------------------------------------------------------------------------
// Head: per node n (one warp):
//   a[j]   = relu( sum_k (L[n,k]+b2[k]) * fc1W[k,j] + fc1b[j] ),  j=0..31
//   z[c]   = sum_j a[j]*fc2W[j,c] + fc2b[c],  c=0..1
//   out[n] = log_softmax(z)
// ---------------------------------------------------------------------------
__global__ __launch_bounds__(256) void head_kernel(
    const float* __restrict__ L, const float* __restrict__ b2,
    const float* __restrict__ fc1W, const float* __restrict__ fc1b,
    const float* __restrict__ fc2W, const float* __restrict__ fc2b,
    float* __restrict__ out, int N)
{
    __shared__ float Wsh[HID * 32];
    __shared__ float b2sh[HID];

    const int tid = threadIdx.x;
    for (int i = tid; i < HID * 32; i += blockDim.x) Wsh[i] = fc1W[i];
    for (int i = tid; i < HID; i += blockDim.x) b2sh[i] = b2[i];
    __syncthreads();

    const int warp = tid >> 5;
    const int lane = tid & 31;
    const int node = blockIdx.x * (blockDim.x >> 5) + warp;
    if (node >= N) return;

    const float* __restrict__ row = L + (size_t)node * HID;
    float a = fc1b[lane];

#pragma unroll 2
    for (int base = 0; base < HID; base += 32) {
        float xk = row[base + lane] + b2sh[base + lane];
#pragma unroll
        for (int kk = 0; kk < 32; kk++) {
            float xv = __shfl_sync(0xffffffffu, xk, kk);
            a = fmaf(xv, Wsh[(base + kk) * 32 + lane], a);
        }
    }
    a = fmaxf(a, 0.f);

    float t0 = a * fc2W[lane * 2 + 0];
    float t1 = a * fc2W[lane * 2 + 1];
#pragma unroll
    for (int off = 16; off > 0; off >>= 1) {
        t0 += __shfl_down_sync(0xffffffffu, t0, off);
        t1 += __shfl_down_sync(0xffffffffu, t1, off);
    }
    if (lane == 0) {
        const float z0 = t0 + fc2b[0];
        const float z1 = t1 + fc2b[1];
        const float m = fmaxf(z0, z1);
        const float lse = m + logf(expf(z0 - m) + expf(z1 - m));
        out[node * 2 + 0] = z0 - lse;
        out[node * 2 + 1] = z1 - lse;
    }
}

// ---------------------------------------------------------------------------
extern "C" void kernel_launch(void* const* d_in, const int* in_sizes, int n_in,
                              void* d_out, int out_size)
{
    const float* inputs    = (const float*)d_in[0];
    const int*   edge_rows = (const int*)  d_in[1];
    const int*   edge_cols = (const int*)  d_in[2];
    const float* edge_vals = (const float*)d_in[3];
    const float* W1        = (const float*)d_in[4];
    const float* b1        = (const float*)d_in[5];
    const float* W2        = (const float*)d_in[6];
    const float* b2        = (const float*)d_in[7];
    const float* fc1W      = (const float*)d_in[8];
    const float* fc1b      = (const float*)d_in[9];
    const float* fc2W      = (const float*)d_in[10];
    const float* fc2b      = (const float*)d_in[11];
    float* out = (float*)d_out;

    const int N = in_sizes[0] / IN_DIM;   // 100000
    const int E = in_sizes[1];            // 3200000

    float* bufA = nullptr;
    float* bufB = nullptr;
    cudaGetSymbolAddress((void**)&bufA, g_bufA);
    cudaGetSymbolAddress((void**)&bufB, g_bufB);

    const size_t featBytes = (size_t)N * HID * sizeof(float);

    dim3 gemmGrid(HID / 64, (N + 63) / 64);

    // Layer 1: S1 = X @ W1
    gemm_kernel<<<gemmGrid, 256>>>(inputs, W1, bufA, N, IN_DIM, HID);

    // H = spmm(S1); H = relu(H + b1)
    cudaMemsetAsync(bufB, 0, featBytes);
    {
        int blocks = (E + 7) / 8;   // 8 warps per block, warp per edge
        spmm_kernel<<<blocks, 256>>>(edge_rows, edge_cols, edge_vals, bufA, bufB, E);
    }
    {
        int n4 = N * HID / 4;
        bias_relu_kernel<<<(n4 + 255) / 256, 256>>>(bufB, b1, n4);
    }

    // Layer 2: S2 = H @ W2
    gemm_kernel<<<gemmGrid, 256>>>(bufB, W2, bufA, N, HID, HID);

    // L = spmm(S2)  (b2 folded into the head)
    cudaMemsetAsync(bufB, 0, featBytes);
    {
        int blocks = (E + 7) / 8;
        spmm_kernel<<<blocks, 256>>>(edge_rows, edge_cols, edge_vals, bufA, bufB, E);
    }

    // Head + log_softmax
    head_kernel<<<(N + 7) / 8, 256>>>(bufB, b2, fc1W, fc1b, fc2W, fc2b, out, N);
}

// round 2
// speedup vs baseline: 2.9989x; 2.9989x over previous
#include <cuda_runtime.h>
#include <cuda_bf16.h>
#include <math.h>

#define N_NODES_MAX 100000
#define E_MAX 3200000
#define IN_DIM 512
#define HID 256
#define SCAN_B 256

// Static device scratch (allocation-free)
__device__ float g_bufA[(size_t)N_NODES_MAX * HID];
__device__ float g_bufB[(size_t)N_NODES_MAX * HID];
__device__ int    g_counts[N_NODES_MAX];        // histogram, then write-ptr
__device__ int    g_rowPtr[N_NODES_MAX + 1];
__device__ int    g_blockSums[(N_NODES_MAX + SCAN_B - 1) / SCAN_B + 1];
__device__ float2 g_csr[E_MAX];                 // (col as int bits, val)

// ---------------------------------------------------------------------------
// Tiled fp32 GEMM: C[M,N] = A[M,K] @ B[K,N]. BM=64,BN=64,BK=16, 256 thr, 4x4.
// ---------------------------------------------------------------------------
__global__ __launch_bounds__(256) void gemm_kernel(
    const float* __restrict__ A, const float* __restrict__ B,
    float* __restrict__ C, int M, int K, int N)
{
    __shared__ float As[16][68];
    __shared__ float Bs[16][64];

    const int tid = threadIdx.x;
    const int tx = tid & 15;
    const int ty = tid >> 4;
    const int rowBase = blockIdx.y * 64;
    const int colBase = blockIdx.x * 64;

    float acc[4][4];
#pragma unroll
    for (int i = 0; i < 4; i++)
#pragma unroll
        for (int j = 0; j < 4; j++) acc[i][j] = 0.f;

    const int aRow = tid >> 2;
    const int aK   = (tid & 3) * 4;
    const int bK   = tid >> 4;
    const int bCol = (tid & 15) * 4;

    for (int k0 = 0; k0 < K; k0 += 16) {
        float4 av = make_float4(0.f, 0.f, 0.f, 0.f);
        const int gr = rowBase + aRow;
        if (gr < M)
            av = *(const float4*)(A + (size_t)gr * K + k0 + aK);
        As[aK + 0][aRow] = av.x;
        As[aK + 1][aRow] = av.y;
        As[aK + 2][aRow] = av.z;
        As[aK + 3][aRow] = av.w;

        float4 bv = *(const float4*)(B + (size_t)(k0 + bK) * N + colBase + bCol);
        *(float4*)&Bs[bK][bCol] = bv;

        __syncthreads();

#pragma unroll
        for (int k = 0; k < 16; k++) {
            float4 a = *(const float4*)&As[k][ty * 4];
            float4 b = *(const float4*)&Bs[k][tx * 4];
            float ar[4] = {a.x, a.y, a.z, a.w};
            float br[4] = {b.x, b.y, b.z, b.w};
#pragma unroll
            for (int i = 0; i < 4; i++)
#pragma unroll
                for (int j = 0; j < 4; j++)
                    acc[i][j] = fmaf(ar[i], br[j], acc[i][j]);
        }
        __syncthreads();
    }

#pragma unroll
    for (int i = 0; i < 4; i++) {
        const int gr = rowBase + ty * 4 + i;
        if (gr < M) {
            float4 v = make_float4(acc[i][0], acc[i][1], acc[i][2], acc[i][3]);
            *(float4*)(C + (size_t)gr * N + colBase + tx * 4) = v;
        }
    }
}

// ---------------------------------------------------------------------------
// CSR build
// ---------------------------------------------------------------------------
__global__ void histogram_kernel(const int* __restrict__ rows, int* __restrict__ counts, int E)
{
    for (int e = blockIdx.x * blockDim.x + threadIdx.x; e < E; e += gridDim.x * blockDim.x)
        atomicAdd(&counts[rows[e]], 1);
}

// Per-block exclusive scan of counts -> rowPtr (local), write block total.
__global__ void scan1_kernel(const int* __restrict__ counts, int* __restrict__ rowPtr,
                             int* __restrict__ blockSums, int n)
{
    __shared__ int sh[SCAN_B];
    const int i = blockIdx.x * SCAN_B + threadIdx.x;
    int v = (i < n) ? counts[i] : 0;
    sh[threadIdx.x] = v;
    __syncthreads();
#pragma unroll
    for (int off = 1; off < SCAN_B; off <<= 1) {
        int t = (threadIdx.x >= off) ? sh[threadIdx.x - off] : 0;
        __syncthreads();
        sh[threadIdx.x] += t;
        __syncthreads();
    }
    if (i < n) rowPtr[i] = sh[threadIdx.x] - v;      // exclusive
    if (threadIdx.x == SCAN_B - 1) blockSums[blockIdx.x] = sh[SCAN_B - 1];
}

// Single-block exclusive scan of block sums (nb <= 512).
__global__ void scan2_kernel(int* __restrict__ blockSums, int nb)
{
    __shared__ int sh[512];
    int v = (threadIdx.x < nb) ? blockSums[threadIdx.x] : 0;
    sh[threadIdx.x] = v;
    __syncthreads();
#pragma unroll
    for (int off = 1; off < 512; off <<= 1) {
        int t = (threadIdx.x >= off) ? sh[threadIdx.x - off] : 0;
        __syncthreads();
        sh[threadIdx.x] += t;
        __syncthreads();
    }
    if (threadIdx.x < nb) blockSums[threadIdx.x] = sh[threadIdx.x] - v;  // exclusive
}

// Add block offsets; also initialize write pointers and rowPtr[n].
__global__ void scan3_kernel(int* __restrict__ rowPtr, const int* __restrict__ blockSums,
                             int* __restrict__ wptr, int n, int total)
{
    const int i = blockIdx.x * SCAN_B + threadIdx.x;
    if (i < n) {
        const int p = rowPtr[i] + blockSums[blockIdx.x];
        rowPtr[i] = p;
        wptr[i]   = p;
    }
    if (i == 0) rowPtr[n] = total;
}

__global__ void scatter_kernel(const int* __restrict__ rows, const int* __restrict__ cols,
                               const float* __restrict__ vals, int* __restrict__ wptr,
                               float2* __restrict__ csr, int E)
{
    for (int e = blockIdx.x * blockDim.x + threadIdx.x; e < E; e += gridDim.x * blockDim.x) {
        const int r = rows[e];
        const int pos = atomicAdd(&wptr[r], 1);
        csr[pos] = make_float2(__int_as_float(cols[e]), vals[e]);
    }
}

// ---------------------------------------------------------------------------
// CSR gather SpMM, fused bias (+optional relu): one warp per destination node.
// H[n,:] = act( sum_{e in row n} val_e * S[col_e, :] + bias )
// ---------------------------------------------------------------------------
template <bool RELU>
__global__ __launch_bounds__(256) void spmm_csr_kernel(
    const int* __restrict__ rowPtr, const float2* __restrict__ csr,
    const float* __restrict__ S, const float* __restrict__ bias,
    float* __restrict__ H, int N)
{
    const int warp = (blockIdx.x * blockDim.x + threadIdx.x) >> 5;
    const int lane = threadIdx.x & 31;
    if (warp >= N) return;

    const int s = rowPtr[warp];
    const int e = rowPtr[warp + 1];

    float4 a0 = make_float4(0.f, 0.f, 0.f, 0.f);
    float4 a1 = make_float4(0.f, 0.f, 0.f, 0.f);

    const float4* __restrict__ S4 = (const float4*)S;

    for (int i = s; i < e; i++) {
        const float2 cv = __ldg(&csr[i]);
        const int   c = __float_as_int(cv.x);
        const float v = cv.y;
        const float4* __restrict__ src = S4 + (size_t)c * (HID / 4);
        const float4 x0 = __ldg(&src[lane]);
        const float4 x1 = __ldg(&src[lane + 32]);
        a0.x = fmaf(v, x0.x, a0.x); a0.y = fmaf(v, x0.y, a0.y);
        a0.z = fmaf(v, x0.z, a0.z); a0.w = fmaf(v, x0.w, a0.w);
        a1.x = fmaf(v, x1.x, a1.x); a1.y = fmaf(v, x1.y, a1.y);
        a1.z = fmaf(v, x1.z, a1.z); a1.w = fmaf(v, x1.w, a1.w);
    }

    const float4* __restrict__ b4 = (const float4*)bias;
    const float4 bb0 = __ldg(&b4[lane]);
    const float4 bb1 = __ldg(&b4[lane + 32]);
    a0.x += bb0.x; a0.y += bb0.y; a0.z += bb0.z; a0.w += bb0.w;
    a1.x += bb1.x; a1.y += bb1.y; a1.z += bb1.z; a1.w += bb1.w;
    if (RELU) {
        a0.x = fmaxf(a0.x, 0.f); a0.y = fmaxf(a0.y, 0.f);
        a0.z = fmaxf(a0.z, 0.f); a0.w = fmaxf(a0.w, 0.f);
        a1.x = fmaxf(a1.x, 0.f); a1.y = fmaxf(a1.y, 0.f);
        a1.z = fmaxf(a1.z, 0.f); a1.w = fmaxf(a1.w, 0.f);
    }

    float4* __restrict__ dst = (float4*)(H + (size_t)warp * HID);
    dst[lane]      = a0;
    dst[lane + 32] = a1;
}

// ---------------------------------------------------------------------------
// Head (b2 already folded into spmm2): per node (one warp):
//   a = relu(L[n,:] @ fc1W + fc1b);  z = a @ fc2W + fc2b;  out = log_softmax(z)
// ---------------------------------------------------------------------------
__global__ __launch_bounds__(256) void head_kernel(
    const float* __restrict__ L,
    const float* __restrict__ fc1W, const float* __restrict__ fc1b,
    const float* __restrict__ fc2W, const float* __restrict__ fc2b,
    float* __restrict__ out, int N)
{
    __shared__ float Wsh[HID * 32];

    const int tid = threadIdx.x;
    for (int i = tid; i < HID * 32; i += blockDim.x) Wsh[i] = fc1W[i];
    __syncthreads();

    const int warp = tid >> 5;
    const int lane = tid & 31;
    const int node = blockIdx.x * (blockDim.x >> 5) + warp;
    if (node >= N) return;

    const float* __restrict__ row = L + (size_t)node * HID;
    float a = fc1b[lane];

#pragma unroll 2
    for (int base = 0; base < HID; base += 32) {
        float xk = row[base + lane];
#pragma unroll
        for (int kk = 0; kk < 32; kk++) {
            float xv = __shfl_sync(0xffffffffu, xk, kk);
            a = fmaf(xv, Wsh[(base + kk) * 32 + lane], a);
        }
    }
    a = fmaxf(a, 0.f);

    float t0 = a * fc2W[lane * 2 + 0];
    float t1 = a * fc2W[lane * 2 + 1];
#pragma unroll
    for (int off = 16; off > 0; off >>= 1) {
        t0 += __shfl_down_sync(0xffffffffu, t0, off);
        t1 += __shfl_down_sync(0xffffffffu, t1, off);
    }
    if (lane == 0) {
        const float z0 = t0 + fc2b[0];
        const float z1 = t1 + fc2b[1];
        const float m = fmaxf(z0, z1);
        const float lse = m + logf(expf(z0 - m) + expf(z1 - m));
        out[node * 2 + 0] = z0 - lse;
        out[node * 2 + 1] = z1 - lse;
    }
}

// ---------------------------------------------------------------------------
extern "C" void kernel_launch(void* const* d_in, const int* in_sizes, int n_in,
                              void* d_out, int out_size)
{
    const float* inputs    = (const float*)d_in[0];
    const int*   edge_rows = (const int*)  d_in[1];
    const int*   edge_cols = (const int*)  d_in[2];
    const float* edge_vals = (const float*)d_in[3];
    const float* W1        = (const float*)d_in[4];
    const float* b1        = (const float*)d_in[5];
    const float* W2        = (const float*)d_in[6];
    const float* b2        = (const float*)d_in[7];
    const float* fc1W      = (const float*)d_in[8];
    const float* fc1b      = (const float*)d_in[9];
    const float* fc2W      = (const float*)d_in[10];
    const float* fc2b      = (const float*)d_in[11];
    float* out = (float*)d_out;

    const int N = in_sizes[0] / IN_DIM;   // 100000
    const int E = in_sizes[1];            // 3200000

    float* bufA; float* bufB;
    int* counts; int* rowPtr; int* blockSums; float2* csr;
    cudaGetSymbolAddress((void**)&bufA, g_bufA);
    cudaGetSymbolAddress((void**)&bufB, g_bufB);
    cudaGetSymbolAddress((void**)&counts, g_counts);
    cudaGetSymbolAddress((void**)&rowPtr, g_rowPtr);
    cudaGetSymbolAddress((void**)&blockSums, g_blockSums);
    cudaGetSymbolAddress((void**)&csr, g_csr);

    const int nScanBlocks = (N + SCAN_B - 1) / SCAN_B;   // 391

    // ---- CSR build (shared by both SpMMs) ----
    cudaMemsetAsync(counts, 0, (size_t)N * sizeof(int));
    histogram_kernel<<<512, 256>>>(edge_rows, counts, E);
    scan1_kernel<<<nScanBlocks, SCAN_B>>>(counts, rowPtr, blockSums, N);
    scan2_kernel<<<1, 512>>>(blockSums, nScanBlocks);
    scan3_kernel<<<nScanBlocks, SCAN_B>>>(rowPtr, blockSums, counts /*wptr*/, N, E);
    scatter_kernel<<<512, 256>>>(edge_rows, edge_cols, edge_vals, counts, csr, E);

    dim3 gemmGrid(HID / 64, (N + 63) / 64);
    const int spmmBlocks = (N + 7) / 8;    // 8 warps/block, warp per node

    // ---- Layer 1: S1 = X @ W1; H = relu(spmm(S1) + b1) ----
    gemm_kernel<<<gemmGrid, 256>>>(inputs, W1, bufA, N, IN_DIM, HID);
    spmm_csr_kernel<true><<<spmmBlocks, 256>>>(rowPtr, csr, bufA, b1, bufB, N);

    // ---- Layer 2: S2 = H @ W2; L = spmm(S2) + b2 ----
    gemm_kernel<<<gemmGrid, 256>>>(bufB, W2, bufA, N, HID, HID);
    spmm_csr_kernel<false><<<spmmBlocks, 256>>>(rowPtr, csr, bufA, b2, bufB, N);

    // ---- Head + log_softmax ----
    head_kernel<<<(N + 7) / 8, 256>>>(bufB, fc1W, fc1b, fc2W, fc2b, out, N);
}

// round 4
// speedup vs baseline: 3.4664x; 1.1559x over previous
#include <cuda_runtime.h>
#include <cuda_fp16.h>
#include <math.h>

#define N_NODES_MAX 100000
#define E_MAX 3200000
#define IN_DIM 512
#define HID 256
#define SCAN_B 256

// Static device scratch (allocation-free)
__device__ float  g_bufA[(size_t)N_NODES_MAX * HID];   // fp32 H / L
__device__ __half g_bufS[(size_t)N_NODES_MAX * HID];   // fp16 support (51 MB, L2-resident)
__device__ int    g_counts[N_NODES_MAX];        // histogram, then write-ptr
__device__ int    g_rowPtr[N_NODES_MAX + 1];
__device__ int    g_blockSums[(N_NODES_MAX + SCAN_B - 1) / SCAN_B + 1];
__device__ float2 g_csr[E_MAX];                 // (col as int bits, val)

// ---------------------------------------------------------------------------
// Tiled fp32 GEMM with fp16 output: C[M,N] = half(A[M,K] @ B[K,N]).
// BM=64,BN=64,BK=16, 256 thr, 4x4 per thread.
// ---------------------------------------------------------------------------
__global__ __launch_bounds__(256) void gemm_f16out_kernel(
    const float* __restrict__ A, const float* __restrict__ B,
    __half* __restrict__ C, int M, int K, int N)
{
    __shared__ float As[16][68];
    __shared__ float Bs[16][64];

    const int tid = threadIdx.x;
    const int tx = tid & 15;
    const int ty = tid >> 4;
    const int rowBase = blockIdx.y * 64;
    const int colBase = blockIdx.x * 64;

    float acc[4][4];
#pragma unroll
    for (int i = 0; i < 4; i++)
#pragma unroll
        for (int j = 0; j < 4; j++) acc[i][j] = 0.f;

    const int aRow = tid >> 2;
    const int aK   = (tid & 3) * 4;
    const int bK   = tid >> 4;
    const int bCol = (tid & 15) * 4;

    for (int k0 = 0; k0 < K; k0 += 16) {
        float4 av = make_float4(0.f, 0.f, 0.f, 0.f);
        const int gr = rowBase + aRow;
        if (gr < M)
            av = *(const float4*)(A + (size_t)gr * K + k0 + aK);
        As[aK + 0][aRow] = av.x;
        As[aK + 1][aRow] = av.y;
        As[aK + 2][aRow] = av.z;
        As[aK + 3][aRow] = av.w;

        float4 bv = *(const float4*)(B + (size_t)(k0 + bK) * N + colBase + bCol);
        *(float4*)&Bs[bK][bCol] = bv;

        __syncthreads();

#pragma unroll
        for (int k = 0; k < 16; k++) {
            float4 a = *(const float4*)&As[k][ty * 4];
            float4 b = *(const float4*)&Bs[k][tx * 4];
            float ar[4] = {a.x, a.y, a.z, a.w};
            float br[4] = {b.x, b.y, b.z, b.w};
#pragma unroll
            for (int i = 0; i < 4; i++)
#pragma unroll
                for (int j = 0; j < 4; j++)
                    acc[i][j] = fmaf(ar[i], br[j], acc[i][j]);
        }
        __syncthreads();
    }

#pragma unroll
    for (int i = 0; i < 4; i++) {
        const int gr = rowBase + ty * 4 + i;
        if (gr < M) {
            __half2 p0 = __float22half2_rn(make_float2(acc[i][0], acc[i][1]));
            __half2 p1 = __float22half2_rn(make_float2(acc[i][2], acc[i][3]));
            uint2 packed = make_uint2(*(unsigned*)&p0, *(unsigned*)&p1);
            *(uint2*)(C + (size_t)gr * N + colBase + tx * 4) = packed;
        }
    }
}

// ---------------------------------------------------------------------------
// CSR build
// ---------------------------------------------------------------------------
__global__ void histogram_kernel(const int* __restrict__ rows, int* __restrict__ counts, int E)
{
    for (int e = blockIdx.x * blockDim.x + threadIdx.x; e < E; e += gridDim.x * blockDim.x)
        atomicAdd(&counts[rows[e]], 1);
}

__global__ void scan1_kernel(const int* __restrict__ counts, int* __restrict__ rowPtr,
                             int* __restrict__ blockSums, int n)
{
    __shared__ int sh[SCAN_B];
    const int i = blockIdx.x * SCAN_B + threadIdx.x;
    int v = (i < n) ? counts[i] : 0;
    sh[threadIdx.x] = v;
    __syncthreads();
#pragma unroll
    for (int off = 1; off < SCAN_B; off <<= 1) {
        int t = (threadIdx.x >= off) ? sh[threadIdx.x - off] : 0;
        __syncthreads();
        sh[threadIdx.x] += t;
        __syncthreads();
    }
    if (i < n) rowPtr[i] = sh[threadIdx.x] - v;      // exclusive
    if (threadIdx.x == SCAN_B - 1) blockSums[blockIdx.x] = sh[SCAN_B - 1];
}

__global__ void scan2_kernel(int* __restrict__ blockSums, int nb)
{
    __shared__ int sh[512];
    int v = (threadIdx.x < nb) ? blockSums[threadIdx.x] : 0;
    sh[threadIdx.x] = v;
    __syncthreads();
#pragma unroll
    for (int off = 1; off < 512; off <<= 1) {
        int t = (threadIdx.x >= off) ? sh[threadIdx.x - off] : 0;
        __syncthreads();
        sh[threadIdx.x] += t;
        __syncthreads();
    }
    if (threadIdx.x < nb) blockSums[threadIdx.x] = sh[threadIdx.x] - v;  // exclusive
}

__global__ void scan3_kernel(int* __restrict__ rowPtr, const int* __restrict__ blockSums,
                             int* __restrict__ wptr, int n, int total)
{
    const int i = blockIdx.x * SCAN_B + threadIdx.x;
    if (i < n) {
        const int p = rowPtr[i] + blockSums[blockIdx.x];
        rowPtr[i] = p;
        wptr[i]   = p;
    }
    if (i == 0) rowPtr[n] = total;
}

__global__ void scatter_kernel(const int* __restrict__ rows, const int* __restrict__ cols,
                               const float* __restrict__ vals, int* __restrict__ wptr,
                               float2* __restrict__ csr, int E)
{
    for (int e = blockIdx.x * blockDim.x + threadIdx.x; e < E; e += gridDim.x * blockDim.x) {
        const int r = rows[e];
        const int pos = atomicAdd(&wptr[r], 1);
        csr[pos] = make_float2(__int_as_float(cols[e]), vals[e]);
    }
}

// ---------------------------------------------------------------------------
// CSR gather SpMM from fp16 source, fused bias (+optional relu).
// One warp per destination node; lane owns cols [lane*8, lane*8+8).
// H[n,:] = act( sum_{e in row n} val_e * Sf16[col_e, :] + bias )
// ---------------------------------------------------------------------------
template <bool RELU>
__global__ __launch_bounds__(256) void spmm_csr_f16_kernel(
    const int* __restrict__ rowPtr, const float2* __restrict__ csr,
    const __half* __restrict__ S, const float* __restrict__ bias,
    float* __restrict__ H, int N)
{
    const int warp = (blockIdx.x * blockDim.x + threadIdx.x) >> 5;
    const int lane = threadIdx.x & 31;
    if (warp >= N) return;

    const int s = rowPtr[warp];
    const int e = rowPtr[warp + 1];

    float acc[8];
#pragma unroll
    for (int j = 0; j < 8; j++) acc[j] = 0.f;

    const float4* __restrict__ S4 = (const float4*)S;   // 8 halves = one float4

    for (int i = s; i < e; i++) {
        const float2 cv = __ldg(&csr[i]);
        const int   c = __float_as_int(cv.x);
        const float v = cv.y;
        const float4 raw = __ldg(&S4[(size_t)c * (HID / 8) + lane]);
        const __half2* h2 = (const __half2*)&raw;
#pragma unroll
        for (int q = 0; q < 4; q++) {
            float2 f = __half22float2(h2[q]);
            acc[q * 2 + 0] = fmaf(v, f.x, acc[q * 2 + 0]);
            acc[q * 2 + 1] = fmaf(v, f.y, acc[q * 2 + 1]);
        }
    }

    const float4* __restrict__ b4 = (const float4*)bias;
    const float4 bb0 = __ldg(&b4[lane * 2 + 0]);
    const float4 bb1 = __ldg(&b4[lane * 2 + 1]);
    float4 o0 = make_float4(acc[0] + bb0.x, acc[1] + bb0.y, acc[2] + bb0.z, acc[3] + bb0.w);
    float4 o1 = make_float4(acc[4] + bb1.x, acc[5] + bb1.y, acc[6] + bb1.z, acc[7] + bb1.w);
    if (RELU) {
        o0.x = fmaxf(o0.x, 0.f); o0.y = fmaxf(o0.y, 0.f);
        o0.z = fmaxf(o0.z, 0.f); o0.w = fmaxf(o0.w, 0.f);
        o1.x = fmaxf(o1.x, 0.f); o1.y = fmaxf(o1.y, 0.f);
        o1.z = fmaxf(o1.z, 0.f); o1.w = fmaxf(o1.w, 0.f);
    }

    float4* __restrict__ dst = (float4*)(H + (size_t)warp * HID);
    dst[lane * 2 + 0] = o0;
    dst[lane * 2 + 1] = o1;
}

// ---------------------------------------------------------------------------
// Head: per node (one warp): a = relu(L @ fc1W + fc1b); z = a @ fc2W + fc2b;
// out = log_softmax(z). (b2 already folded into spmm2.)
// ---------------------------------------------------------------------------
__global__ __launch_bounds__(256) void head_kernel(
    const float* __restrict__ L,
    const float* __restrict__ fc1W, const float* __restrict__ fc1b,
    const float* __restrict__ fc2W, const float* __restrict__ fc2b,
    float* __restrict__ out, int N)
{
    __shared__ float Wsh[HID * 32];

    const int tid = threadIdx.x;
    for (int i = tid; i < HID * 32; i += blockDim.x) Wsh[i] = fc1W[i];
    __syncthreads();

    const int warp = tid >> 5;
    const int lane = tid & 31;
    const int node = blockIdx.x * (blockDim.x >> 5) + warp;
    if (node >= N) return;

    const float* __restrict__ row = L + (size_t)node * HID;
    float a = fc1b[lane];

#pragma unroll 2
    for (int base = 0; base < HID; base += 32) {
        float xk = row[base + lane];
#pragma unroll
        for (int kk = 0; kk < 32; kk++) {
            float xv = __shfl_sync(0xffffffffu, xk, kk);
            a = fmaf(xv, Wsh[(base + kk) * 32 + lane], a);
        }
    }
    a = fmaxf(a, 0.f);

    float t0 = a * fc2W[lane * 2 + 0];
    float t1 = a * fc2W[lane * 2 + 1];
#pragma unroll
    for (int off = 16; off > 0; off >>= 1) {
        t0 += __shfl_down_sync(0xffffffffu, t0, off);
        t1 += __shfl_down_sync(0xffffffffu, t1, off);
    }
    if (lane == 0) {
        const float z0 = t0 + fc2b[0];
        const float z1 = t1 + fc2b[1];
        const float m = fmaxf(z0, z1);
        const float lse = m + logf(expf(z0 - m) + expf(z1 - m));
        out[node * 2 + 0] = z0 - lse;
        out[node * 2 + 1] = z1 - lse;
    }
}

// ---------------------------------------------------------------------------
extern "C" void kernel_launch(void* const* d_in, const int* in_sizes, int n_in,
                              void* d_out, int out_size)
{
    const float* inputs    = (const float*)d_in[0];
    const int*   edge_rows = (const int*)  d_in[1];
    const int*   edge_cols = (const int*)  d_in[2];
    const float* edge_vals = (const float*)d_in[3];
    const float* W1        = (const float*)d_in[4];
    const float* b1        = (const float*)d_in[5];
    const float* W2        = (const float*)d_in[6];
    const float* b2        = (const float*)d_in[7];
    const float* fc1W      = (const float*)d_in[8];
    const float* fc1b      = (const float*)d_in[9];
    const float* fc2W      = (const float*)d_in[10];
    const float* fc2b      = (const float*)d_in[11];
    float* out = (float*)d_out;

    const int N = in_sizes[0] / IN_DIM;   // 100000
    const int E = in_sizes[1];            // 3200000

    float* bufA; __half* bufS;
    int* counts; int* rowPtr; int* blockSums; float2* csr;
    cudaGetSymbolAddress((void**)&bufA, g_bufA);
    cudaGetSymbolAddress((void**)&bufS, g_bufS);
    cudaGetSymbolAddress((void**)&counts, g_counts);
    cudaGetSymbolAddress((void**)&rowPtr, g_rowPtr);
    cudaGetSymbolAddress((void**)&blockSums, g_blockSums);
    cudaGetSymbolAddress((void**)&csr, g_csr);

    const int nScanBlocks = (N + SCAN_B - 1) / SCAN_B;   // 391

    // ---- CSR build (shared by both SpMMs) ----
    cudaMemsetAsync(counts, 0, (size_t)N * sizeof(int));
    histogram_kernel<<<512, 256>>>(edge_rows, counts, E);
    scan1_kernel<<<nScanBlocks, SCAN_B>>>(counts, rowPtr, blockSums, N);
    scan2_kernel<<<1, 512>>>(blockSums, nScanBlocks);
    scan3_kernel<<<nScanBlocks, SCAN_B>>>(rowPtr, blockSums, counts /*wptr*/, N, E);
    scatter_kernel<<<512, 256>>>(edge_rows, edge_cols, edge_vals, counts, csr, E);

    dim3 gemmGrid(HID / 64, (N + 63) / 64);
    const int spmmBlocks = (N + 7) / 8;    // 8 warps/block, warp per node

    // ---- Layer 1: S1 = f16(X @ W1); H = relu(spmm(S1) + b1) ----
    gemm_f16out_kernel<<<gemmGrid, 256>>>(inputs, W1, bufS, N, IN_DIM, HID);
    spmm_csr_f16_kernel<true><<<spmmBlocks, 256>>>(rowPtr, csr, bufS, b1, bufA, N);

    // ---- Layer 2: S2 = f16(H @ W2); L = spmm(S2) + b2 ----
    gemm_f16out_kernel<<<gemmGrid, 256>>>(bufA, W2, bufS, N, HID, HID);
    spmm_csr_f16_kernel<false><<<spmmBlocks, 256>>>(rowPtr, csr, bufS, b2, bufA, N);

    // ---- Head + log_softmax ----
    head_kernel<<<(N + 7) / 8, 256>>>(bufA, fc1W, fc1b, fc2W, fc2b, out, N);
}

// round 5
// speedup vs baseline: 6.0116x; 1.7342x over previous
#include <cuda_runtime.h>
#include <cuda_fp16.h>
#include <mma.h>
#include <math.h>

using namespace nvcuda;

#define N_NODES_MAX 100000
#define E_MAX 3200000
#define IN_DIM 512
#define HID 256
#define SCAN_B 256

#define BM 128
#define BN 64
#define BK 32
#define APAD 8
#define BPAD 8

// Static device scratch (allocation-free)
__device__ float  g_bufA[(size_t)N_NODES_MAX * HID];   // fp32 L (spmm2 out)
__device__ __half g_bufS[(size_t)N_NODES_MAX * HID];   // fp16 support S (gather source)
__device__ __half g_bufH[(size_t)N_NODES_MAX * HID];   // fp16 H (layer-1 activations)
__device__ int    g_counts[N_NODES_MAX];
__device__ int    g_rowPtr[N_NODES_MAX + 1];
__device__ int    g_blockSums[(N_NODES_MAX + SCAN_B - 1) / SCAN_B + 1];
__device__ float2 g_csr[E_MAX];                 // (col as int bits, val)

// ---------------------------------------------------------------------------
// Tensor-core GEMM: C[M,N] = half(A[M,K] @ B[K,N]); A fp32 or fp16 (converted
// to fp16 in the loader), B fp32 weights, fp32 accumulate, fp16 output.
// BM=128, BN=64, BK=32, 256 threads = 8 warps (4 along M x 2 along N),
// warp tile 32x32 = 2x2 wmma m16n16k16 fragments.
// ---------------------------------------------------------------------------
template <typename TA>
__global__ __launch_bounds__(256) void gemm_tc_kernel(
    const TA* __restrict__ A, const float* __restrict__ B,
    __half* __restrict__ C, int M, int K, int N)
{
    __shared__ __half As[BM][BK + APAD];
    __shared__ __half Bs[BK][BN + BPAD];
    __shared__ float  stage[8][16 * 16];

    const int tid = threadIdx.x;
    const int wid = tid >> 5;
    const int lane = tid & 31;
    const int warpM = wid & 3;          // 0..3 -> 32 rows each
    const int warpN = wid >> 2;         // 0..1 -> 32 cols each
    const int rowBase = blockIdx.y * BM;
    const int colBase = blockIdx.x * BN;

    wmma::fragment<wmma::accumulator, 16, 16, 16, float> acc[2][2];
#pragma unroll
    for (int i = 0; i < 2; i++)
#pragma unroll
        for (int j = 0; j < 2; j++) wmma::fill_fragment(acc[i][j], 0.f);

    for (int k0 = 0; k0 < K; k0 += BK) {
        // ---- Load A tile (BM x BK), convert to fp16 ----
#pragma unroll
        for (int p = 0; p < 4; p++) {
            const int idx = tid + p * 256;       // 0..1023
            const int r  = idx >> 3;             // 0..127
            const int cg = (idx & 7) * 4;        // 0,4,...,28
            const int gr = rowBase + r;
            if constexpr (sizeof(TA) == 4) {
                float4 v = make_float4(0.f, 0.f, 0.f, 0.f);
                if (gr < M) v = *(const float4*)((const float*)A + (size_t)gr * K + k0 + cg);
                __half2 h0 = __float22half2_rn(make_float2(v.x, v.y));
                __half2 h1 = __float22half2_rn(make_float2(v.z, v.w));
                *(__half2*)&As[r][cg]     = h0;
                *(__half2*)&As[r][cg + 2] = h1;
            } else {
                uint2 v = make_uint2(0u, 0u);
                if (gr < M) v = *(const uint2*)((const __half*)A + (size_t)gr * K + k0 + cg);
                *(uint2*)&As[r][cg] = v;
            }
        }
        // ---- Load B tile (BK x BN), convert to fp16 ----
#pragma unroll
        for (int p = 0; p < 2; p++) {
            const int idx = tid + p * 256;       // 0..511
            const int r  = idx >> 4;             // 0..31
            const int cg = (idx & 15) * 4;       // 0..60
            float4 v = *(const float4*)(B + (size_t)(k0 + r) * N + colBase + cg);
            __half2 h0 = __float22half2_rn(make_float2(v.x, v.y));
            __half2 h1 = __float22half2_rn(make_float2(v.z, v.w));
            *(__half2*)&Bs[r][cg]     = h0;
            *(__half2*)&Bs[r][cg + 2] = h1;
        }
        __syncthreads();

#pragma unroll
        for (int kk = 0; kk < BK; kk += 16) {
            wmma::fragment<wmma::matrix_a, 16, 16, 16, __half, wmma::row_major> af[2];
            wmma::fragment<wmma::matrix_b, 16, 16, 16, __half, wmma::row_major> bf[2];
#pragma unroll
            for (int i = 0; i < 2; i++)
                wmma::load_matrix_sync(af[i], &As[warpM * 32 + i * 16][kk], BK + APAD);
#pragma unroll
            for (int j = 0; j < 2; j++)
                wmma::load_matrix_sync(bf[j], &Bs[kk][warpN * 32 + j * 16], BN + BPAD);
#pragma unroll
            for (int i = 0; i < 2; i++)
#pragma unroll
                for (int j = 0; j < 2; j++)
                    wmma::mma_sync(acc[i][j], af[i], bf[j], acc[i][j]);
        }
        __syncthreads();
    }

    // ---- Epilogue: fp32 acc -> fp16 C via per-warp smem staging ----
    float* st = &stage[wid][0];
    const int lr = lane >> 1;            // 0..15
    const int lc = (lane & 1) * 8;       // 0 or 8
#pragma unroll
    for (int i = 0; i < 2; i++) {
#pragma unroll
        for (int j = 0; j < 2; j++) {
            wmma::store_matrix_sync(st, acc[i][j], 16, wmma::mem_row_major);
            __syncwarp();
            const int gr = rowBase + warpM * 32 + i * 16 + lr;
            if (gr < M) {
                const float* src = st + lr * 16 + lc;
                __half2 h0 = __float22half2_rn(make_float2(src[0], src[1]));
                __half2 h1 = __float22half2_rn(make_float2(src[2], src[3]));
                __half2 h2 = __float22half2_rn(make_float2(src[4], src[5]));
                __half2 h3 = __float22half2_rn(make_float2(src[6], src[7]));
                uint4 packed;
                packed.x = *(unsigned*)&h0; packed.y = *(unsigned*)&h1;
                packed.z = *(unsigned*)&h2; packed.w = *(unsigned*)&h3;
                const int gc = colBase + warpN * 32 + j * 16 + lc;
                *(uint4*)(C + (size_t)gr * N + gc) = packed;
            }
            __syncwarp();
        }
    }
}

// ---------------------------------------------------------------------------
// CSR build
// ---------------------------------------------------------------------------
__global__ void histogram_kernel(const int* __restrict__ rows, int* __restrict__ counts, int E)
{
    for (int e = blockIdx.x * blockDim.x + threadIdx.x; e < E; e += gridDim.x * blockDim.x)
        atomicAdd(&counts[rows[e]], 1);
}

__global__ void scan1_kernel(const int* __restrict__ counts, int* __restrict__ rowPtr,
                             int* __restrict__ blockSums, int n)
{
    __shared__ int sh[SCAN_B];
    const int i = blockIdx.x * SCAN_B + threadIdx.x;
    int v = (i < n) ? counts[i] : 0;
    sh[threadIdx.x] = v;
    __syncthreads();
#pragma unroll
    for (int off = 1; off < SCAN_B; off <<= 1) {
        int t = (threadIdx.x >= off) ? sh[threadIdx.x - off] : 0;
        __syncthreads();
        sh[threadIdx.x] += t;
        __syncthreads();
    }
    if (i < n) rowPtr[i] = sh[threadIdx.x] - v;      // exclusive
    if (threadIdx.x == SCAN_B - 1) blockSums[blockIdx.x] = sh[SCAN_B - 1];
}

__global__ void scan2_kernel(int* __restrict__ blockSums, int nb)
{
    __shared__ int sh[512];
    int v = (threadIdx.x < nb) ? blockSums[threadIdx.x] : 0;
    sh[threadIdx.x] = v;
    __syncthreads();
#pragma unroll
    for (int off = 1; off < 512; off <<= 1) {
        int t = (threadIdx.x >= off) ? sh[threadIdx.x - off] : 0;
        __syncthreads();
        sh[threadIdx.x] += t;
        __syncthreads();
    }
    if (threadIdx.x < nb) blockSums[threadIdx.x] = sh[threadIdx.x] - v;  // exclusive
}

__global__ void scan3_kernel(int* __restrict__ rowPtr, const int* __restrict__ blockSums,
                             int* __restrict__ wptr, int n, int total)
{
    const int i = blockIdx.x * SCAN_B + threadIdx.x;
    if (i < n) {
        const int p = rowPtr[i] + blockSums[blockIdx.x];
        rowPtr[i] = p;
        wptr[i]   = p;
    }
    if (i == 0) rowPtr[n] = total;
}

__global__ void scatter_kernel(const int* __restrict__ rows, const int* __restrict__ cols,
                               const float* __restrict__ vals, int* __restrict__ wptr,
                               float2* __restrict__ csr, int E)
{
    for (int e = blockIdx.x * blockDim.x + threadIdx.x; e < E; e += gridDim.x * blockDim.x) {
        const int r = rows[e];
        const int pos = atomicAdd(&wptr[r], 1);
        csr[pos] = make_float2(__int_as_float(cols[e]), vals[e]);
    }
}

// ---------------------------------------------------------------------------
// CSR gather SpMM from fp16 source, fused bias (+optional relu), templated
// output type (fp16 for H, fp32 for L). One warp per destination node.
// ---------------------------------------------------------------------------
template <bool RELU, bool OUT_HALF>
__global__ __launch_bounds__(256) void spmm_csr_f16_kernel(
    const int* __restrict__ rowPtr, const float2* __restrict__ csr,
    const __half* __restrict__ S, const float* __restrict__ bias,
    void* __restrict__ Hout, int N)
{
    const int warp = (blockIdx.x * blockDim.x + threadIdx.x) >> 5;
    const int lane = threadIdx.x & 31;
    if (warp >= N) return;

    const int s = rowPtr[warp];
    const int e = rowPtr[warp + 1];

    float acc[8];
#pragma unroll
    for (int j = 0; j < 8; j++) acc[j] = 0.f;

    const float4* __restrict__ S4 = (const float4*)S;   // 8 halves per float4

    for (int i = s; i < e; i++) {
        const float2 cv = __ldg(&csr[i]);
        const int   c = __float_as_int(cv.x);
        const float v = cv.y;
        const float4 raw = __ldg(&S4[(size_t)c * (HID / 8) + lane]);
        const __half2* h2 = (const __half2*)&raw;
#pragma unroll
        for (int q = 0; q < 4; q++) {
            float2 f = __half22float2(h2[q]);
            acc[q * 2 + 0] = fmaf(v, f.x, acc[q * 2 + 0]);
            acc[q * 2 + 1] = fmaf(v, f.y, acc[q * 2 + 1]);
        }
    }

    const float4* __restrict__ b4 = (const float4*)bias;
    const float4 bb0 = __ldg(&b4[lane * 2 + 0]);
    const float4 bb1 = __ldg(&b4[lane * 2 + 1]);
#pragma unroll
    for (int q = 0; q < 4; q++) {
        acc[q]     += ((const float*)&bb0)[q];
        acc[q + 4] += ((const float*)&bb1)[q];
    }
    if (RELU) {
#pragma unroll
        for (int j = 0; j < 8; j++) acc[j] = fmaxf(acc[j], 0.f);
    }

    if (OUT_HALF) {
        __half2 h0 = __float22half2_rn(make_float2(acc[0], acc[1]));
        __half2 h1 = __float22half2_rn(make_float2(acc[2], acc[3]));
        __half2 h2 = __float22half2_rn(make_float2(acc[4], acc[5]));
        __half2 h3 = __float22half2_rn(make_float2(acc[6], acc[7]));
        uint4 packed;
        packed.x = *(unsigned*)&h0; packed.y = *(unsigned*)&h1;
        packed.z = *(unsigned*)&h2; packed.w = *(unsigned*)&h3;
        *((uint4*)((__half*)Hout + (size_t)warp * HID) + lane) = packed;
    } else {
        float4* __restrict__ dst = (float4*)((float*)Hout + (size_t)warp * HID);
        dst[lane * 2 + 0] = make_float4(acc[0], acc[1], acc[2], acc[3]);
        dst[lane * 2 + 1] = make_float4(acc[4], acc[5], acc[6], acc[7]);
    }
}

// ---------------------------------------------------------------------------
// Head: per node (one warp): a = relu(L @ fc1W + fc1b); z = a @ fc2W + fc2b;
// out = log_softmax(z). (b2 already folded into spmm2.)
// ---------------------------------------------------------------------------
__global__ __launch_bounds__(256) void head_kernel(
    const float* __restrict__ L,
    const float* __restrict__ fc1W, const float* __restrict__ fc1b,
    const float* __restrict__ fc2W, const float* __restrict__ fc2b,
    float* __restrict__ out, int N)
{
    __shared__ float Wsh[HID * 32];

    const int tid = threadIdx.x;
    for (int i = tid; i < HID * 32; i += blockDim.x) Wsh[i] = fc1W[i];
    __syncthreads();

    const int warp = tid >> 5;
    const int lane = tid & 31;
    const int node = blockIdx.x * (blockDim.x >> 5) + warp;
    if (node >= N) return;

    const float* __restrict__ row = L + (size_t)node * HID;
    float a = fc1b[lane];

#pragma unroll 2
    for (int base = 0; base < HID; base += 32) {
        float xk = row[base + lane];
#pragma unroll
        for (int kk = 0; kk < 32; kk++) {
            float xv = __shfl_sync(0xffffffffu, xk, kk);
            a = fmaf(xv, Wsh[(base + kk) * 32 + lane], a);
        }
    }
    a = fmaxf(a, 0.f);

    float t0 = a * fc2W[lane * 2 + 0];
    float t1 = a * fc2W[lane * 2 + 1];
#pragma unroll
    for (int off = 16; off > 0; off >>= 1) {
        t0 += __shfl_down_sync(0xffffffffu, t0, off);
        t1 += __shfl_down_sync(0xffffffffu, t1, off);
    }
    if (lane == 0) {
        const float z0 = t0 + fc2b[0];
        const float z1 = t1 + fc2b[1];
        const float m = fmaxf(z0, z1);
        const float lse = m + logf(expf(z0 - m) + expf(z1 - m));
        out[node * 2 + 0] = z0 - lse;
        out[node * 2 + 1] = z1 - lse;
    }
}

// ---------------------------------------------------------------------------
extern "C" void kernel_launch(void* const* d_in, const int* in_sizes, int n_in,
                              void* d_out, int out_size)
{
    const float* inputs    = (const float*)d_in[0];
    const int*   edge_rows = (const int*)  d_in[1];
    const int*   edge_cols = (const int*)  d_in[2];
    const float* edge_vals = (const float*)d_in[3];
    const float* W1        = (const float*)d_in[4];
    const float* b1        = (const float*)d_in[5];
    const float* W2        = (const float*)d_in[6];
    const float* b2        = (const float*)d_in[7];
    const float* fc1W      = (const float*)d_in[8];
    const float* fc1b      = (const float*)d_in[9];
    const float* fc2W      = (const float*)d_in[10];
    const float* fc2b      = (const float*)d_in[11];
    float* out = (float*)d_out;

    const int N = in_sizes[0] / IN_DIM;   // 100000
    const int E = in_sizes[1];            // 3200000

    float* bufA; __half* bufS; __half* bufH;
    int* counts; int* rowPtr; int* blockSums; float2* csr;
    cudaGetSymbolAddress((void**)&bufA, g_bufA);
    cudaGetSymbolAddress((void**)&bufS, g_bufS);
    cudaGetSymbolAddress((void**)&bufH, g_bufH);
    cudaGetSymbolAddress((void**)&counts, g_counts);
    cudaGetSymbolAddress((void**)&rowPtr, g_rowPtr);
    cudaGetSymbolAddress((void**)&blockSums, g_blockSums);
    cudaGetSymbolAddress((void**)&csr, g_csr);

    const int nScanBlocks = (N + SCAN_B - 1) / SCAN_B;   // 391

    // ---- CSR build (shared by both SpMMs) ----
    cudaMemsetAsync(counts, 0, (size_t)N * sizeof(int));
    histogram_kernel<<<512, 256>>>(edge_rows, counts, E);
    scan1_kernel<<<nScanBlocks, SCAN_B>>>(counts, rowPtr, blockSums, N);
    scan2_kernel<<<1, 512>>>(blockSums, nScanBlocks);
    scan3_kernel<<<nScanBlocks, SCAN_B>>>(rowPtr, blockSums, counts /*wptr*/, N, E);
    scatter_kernel<<<512, 256>>>(edge_rows, edge_cols, edge_vals, counts, csr, E);

    dim3 gemmGrid(HID / BN, (N + BM - 1) / BM);
    const int spmmBlocks = (N + 7) / 8;    // 8 warps/block, warp per node

    // ---- Layer 1: S1 = f16(X @ W1); H = f16(relu(spmm(S1) + b1)) ----
    gemm_tc_kernel<float><<<gemmGrid, 256>>>(inputs, W1, bufS, N, IN_DIM, HID);
    spmm_csr_f16_kernel<true, true><<<spmmBlocks, 256>>>(rowPtr, csr, bufS, b1, bufH, N);

    // ---- Layer 2: S2 = f16(H @ W2); L = spmm(S2) + b2 (fp32) ----
    gemm_tc_kernel<__half><<<gemmGrid, 256>>>(bufH, W2, bufS, N, HID, HID);
    spmm_csr_f16_kernel<false, false><<<spmmBlocks, 256>>>(rowPtr, csr, bufS, b2, bufA, N);

    // ---- Head + log_softmax ----
    head_kernel<<<(N + 7) / 8, 256>>>(bufA, fc1W, fc1b, fc2W, fc2b, out, N);
}

// round 6
// speedup vs baseline: 6.5785x; 1.0943x over previous
#include <cuda_runtime.h>
#include <cuda_fp16.h>
#include <mma.h>
#include <math.h>

using namespace nvcuda;

#define N_NODES_MAX 100000
#define E_MAX 3200000
#define IN_DIM 512
#define HID 256
#define SCAN_B 256

// GEMM tiles: full-width N so A is read exactly once.
#define BM 64
#define BN 256
#define BK 32
#define APAD 8
#define BPAD 8

// Static device scratch (allocation-free)
__device__ float  g_bufA[(size_t)N_NODES_MAX * HID];   // fp32 L (spmm2 out)
__device__ __half g_bufS[(size_t)N_NODES_MAX * HID];   // fp16 support S (gather source)
__device__ __half g_bufH[(size_t)N_NODES_MAX * HID];   // fp16 H (layer-1 activations)
__device__ int    g_counts[N_NODES_MAX];
__device__ int    g_rowPtr[N_NODES_MAX + 1];
__device__ int    g_blockSums[(N_NODES_MAX + SCAN_B - 1) / SCAN_B + 1];
__device__ float2 g_csr[E_MAX];                 // (col as int bits, val)

// ---------------------------------------------------------------------------
// Tensor-core GEMM: C[M,N] = half(A[M,K] @ B[K,N]); A fp32 or fp16 (converted
// to fp16 in the loader), B fp32 weights -> fp16, fp32 accumulate, fp16 out.
// BM=64, BN=256, BK=32, 256 threads = 8 warps (2 along M x 4 along N),
// warp tile 32x64 = 2x4 wmma m16n16k16 fragments.
// ---------------------------------------------------------------------------
template <typename TA>
__global__ __launch_bounds__(256) void gemm_tc_kernel(
    const TA* __restrict__ A, const float* __restrict__ B,
    __half* __restrict__ C, int M, int K, int N)
{
    __shared__ __half As[BM][BK + APAD];
    __shared__ __half Bs[BK][BN + BPAD];
    __shared__ float  stage[8][16 * 16];

    const int tid = threadIdx.x;
    const int wid = tid >> 5;
    const int lane = tid & 31;
    const int warpM = wid & 1;          // 0..1 -> 32 rows each
    const int warpN = wid >> 1;         // 0..3 -> 64 cols each
    const int rowBase = blockIdx.x * BM;

    wmma::fragment<wmma::accumulator, 16, 16, 16, float> acc[2][4];
#pragma unroll
    for (int i = 0; i < 2; i++)
#pragma unroll
        for (int j = 0; j < 4; j++) wmma::fill_fragment(acc[i][j], 0.f);

    for (int k0 = 0; k0 < K; k0 += BK) {
        // ---- Load A tile (BM x BK = 64x32), convert to fp16 ----
#pragma unroll
        for (int p = 0; p < 2; p++) {
            const int idx = tid + p * 256;       // 0..511
            const int r  = idx >> 3;             // 0..63
            const int cg = (idx & 7) * 4;        // 0,4,...,28
            const int gr = rowBase + r;
            if constexpr (sizeof(TA) == 4) {
                float4 v = make_float4(0.f, 0.f, 0.f, 0.f);
                if (gr < M) v = *(const float4*)((const float*)A + (size_t)gr * K + k0 + cg);
                __half2 h0 = __float22half2_rn(make_float2(v.x, v.y));
                __half2 h1 = __float22half2_rn(make_float2(v.z, v.w));
                *(__half2*)&As[r][cg]     = h0;
                *(__half2*)&As[r][cg + 2] = h1;
            } else {
                uint2 v = make_uint2(0u, 0u);
                if (gr < M) v = *(const uint2*)((const __half*)A + (size_t)gr * K + k0 + cg);
                *(uint2*)&As[r][cg] = v;
            }
        }
        // ---- Load B tile (BK x BN = 32x256), convert to fp16 ----
#pragma unroll
        for (int p = 0; p < 8; p++) {
            const int idx = tid + p * 256;       // 0..2047
            const int r  = idx >> 6;             // 0..31
            const int cg = (idx & 63) * 4;       // 0..252
            float4 v = *(const float4*)(B + (size_t)(k0 + r) * N + cg);
            __half2 h0 = __float22half2_rn(make_float2(v.x, v.y));
            __half2 h1 = __float22half2_rn(make_float2(v.z, v.w));
            *(__half2*)&Bs[r][cg]     = h0;
            *(__half2*)&Bs[r][cg + 2] = h1;
        }
        __syncthreads();

#pragma unroll
        for (int kk = 0; kk < BK; kk += 16) {
            wmma::fragment<wmma::matrix_a, 16, 16, 16, __half, wmma::row_major> af[2];
            wmma::fragment<wmma::matrix_b, 16, 16, 16, __half, wmma::row_major> bf[4];
#pragma unroll
            for (int i = 0; i < 2; i++)
                wmma::load_matrix_sync(af[i], &As[warpM * 32 + i * 16][kk], BK + APAD);
#pragma unroll
            for (int j = 0; j < 4; j++)
                wmma::load_matrix_sync(bf[j], &Bs[kk][warpN * 64 + j * 16], BN + BPAD);
#pragma unroll
            for (int i = 0; i < 2; i++)
#pragma unroll
                for (int j = 0; j < 4; j++)
                    wmma::mma_sync(acc[i][j], af[i], bf[j], acc[i][j]);
        }
        __syncthreads();
    }

    // ---- Epilogue: fp32 acc -> fp16 C via per-warp smem staging ----
    float* st = &stage[wid][0];
    const int lr = lane >> 1;            // 0..15
    const int lc = (lane & 1) * 8;       // 0 or 8
#pragma unroll
    for (int i = 0; i < 2; i++) {
#pragma unroll
        for (int j = 0; j < 4; j++) {
            wmma::store_matrix_sync(st, acc[i][j], 16, wmma::mem_row_major);
            __syncwarp();
            const int gr = rowBase + warpM * 32 + i * 16 + lr;
            if (gr < M) {
                const float* src = st + lr * 16 + lc;
                __half2 h0 = __float22half2_rn(make_float2(src[0], src[1]));
                __half2 h1 = __float22half2_rn(make_float2(src[2], src[3]));
                __half2 h2 = __float22half2_rn(make_float2(src[4], src[5]));
                __half2 h3 = __float22half2_rn(make_float2(src[6], src[7]));
                uint4 packed;
                packed.x = *(unsigned*)&h0; packed.y = *(unsigned*)&h1;
                packed.z = *(unsigned*)&h2; packed.w = *(unsigned*)&h3;
                const int gc = warpN * 64 + j * 16 + lc;
                *(uint4*)(C + (size_t)gr * N + gc) = packed;
            }
            __syncwarp();
        }
    }
}

// ---------------------------------------------------------------------------
// CSR build
// ---------------------------------------------------------------------------
__global__ void histogram_kernel(const int* __restrict__ rows, int* __restrict__ counts, int E)
{
    for (int e = blockIdx.x * blockDim.x + threadIdx.x; e < E; e += gridDim.x * blockDim.x)
        atomicAdd(&counts[rows[e]], 1);
}

__global__ void scan1_kernel(const int* __restrict__ counts, int* __restrict__ rowPtr,
                             int* __restrict__ blockSums, int n)
{
    __shared__ int sh[SCAN_B];
    const int i = blockIdx.x * SCAN_B + threadIdx.x;
    int v = (i < n) ? counts[i] : 0;
    sh[threadIdx.x] = v;
    __syncthreads();
#pragma unroll
    for (int off = 1; off < SCAN_B; off <<= 1) {
        int t = (threadIdx.x >= off) ? sh[threadIdx.x - off] : 0;
        __syncthreads();
        sh[threadIdx.x] += t;
        __syncthreads();
    }
    if (i < n) rowPtr[i] = sh[threadIdx.x] - v;      // exclusive
    if (threadIdx.x == SCAN_B - 1) blockSums[blockIdx.x] = sh[SCAN_B - 1];
}

__global__ void scan2_kernel(int* __restrict__ blockSums, int nb)
{
    __shared__ int sh[512];
    int v = (threadIdx.x < nb) ? blockSums[threadIdx.x] : 0;
    sh[threadIdx.x] = v;
    __syncthreads();
#pragma unroll
    for (int off = 1; off < 512; off <<= 1) {
        int t = (threadIdx.x >= off) ? sh[threadIdx.x - off] : 0;
        __syncthreads();
        sh[threadIdx.x] += t;
        __syncthreads();
    }
    if (threadIdx.x < nb) blockSums[threadIdx.x] = sh[threadIdx.x] - v;  // exclusive
}

__global__ void scan3_kernel(int* __restrict__ rowPtr, const int* __restrict__ blockSums,
                             int* __restrict__ wptr, int n, int total)
{
    const int i = blockIdx.x * SCAN_B + threadIdx.x;
    if (i < n) {
        const int p = rowPtr[i] + blockSums[blockIdx.x];
        rowPtr[i] = p;
        wptr[i]   = p;
    }
    if (i == 0) rowPtr[n] = total;
}

__global__ void scatter_kernel(const int* __restrict__ rows, const int* __restrict__ cols,
                               const float* __restrict__ vals, int* __restrict__ wptr,
                               float2* __restrict__ csr, int E)
{
    for (int e = blockIdx.x * blockDim.x + threadIdx.x; e < E; e += gridDim.x * blockDim.x) {
        const int r = rows[e];
        const int pos = atomicAdd(&wptr[r], 1);
        csr[pos] = make_float2(__int_as_float(cols[e]), vals[e]);
    }
}

// ---------------------------------------------------------------------------
// CSR gather SpMM from fp16 source, fused bias (+optional relu), templated
// output type (fp16 for H, fp32 for L). One warp per destination node.
// 2-edge unrolled inner loop for memory-level parallelism.
// ---------------------------------------------------------------------------
template <bool RELU, bool OUT_HALF>
__global__ __launch_bounds__(256) void spmm_csr_f16_kernel(
    const int* __restrict__ rowPtr, const float2* __restrict__ csr,
    const __half* __restrict__ S, const float* __restrict__ bias,
    void* __restrict__ Hout, int N)
{
    const int warp = (blockIdx.x * blockDim.x + threadIdx.x) >> 5;
    const int lane = threadIdx.x & 31;
    if (warp >= N) return;

    const int s = rowPtr[warp];
    const int e = rowPtr[warp + 1];

    float acc[8];
#pragma unroll
    for (int j = 0; j < 8; j++) acc[j] = 0.f;

    const float4* __restrict__ S4 = (const float4*)S;   // 8 halves per float4

    int i = s;
    for (; i + 1 < e; i += 2) {
        const float2 cv0 = __ldg(&csr[i]);
        const float2 cv1 = __ldg(&csr[i + 1]);
        const int   c0 = __float_as_int(cv0.x);
        const int   c1 = __float_as_int(cv1.x);
        const float v0 = cv0.y;
        const float v1 = cv1.y;
        const float4 r0 = __ldg(&S4[(size_t)c0 * (HID / 8) + lane]);
        const float4 r1 = __ldg(&S4[(size_t)c1 * (HID / 8) + lane]);
        const __half2* a2 = (const __half2*)&r0;
        const __half2* b2 = (const __half2*)&r1;
#pragma unroll
        for (int q = 0; q < 4; q++) {
            float2 fa = __half22float2(a2[q]);
            float2 fb = __half22float2(b2[q]);
            acc[q * 2 + 0] = fmaf(v0, fa.x, acc[q * 2 + 0]);
            acc[q * 2 + 1] = fmaf(v0, fa.y, acc[q * 2 + 1]);
            acc[q * 2 + 0] = fmaf(v1, fb.x, acc[q * 2 + 0]);
            acc[q * 2 + 1] = fmaf(v1, fb.y, acc[q * 2 + 1]);
        }
    }
    if (i < e) {
        const float2 cv = __ldg(&csr[i]);
        const int   c = __float_as_int(cv.x);
        const float v = cv.y;
        const float4 raw = __ldg(&S4[(size_t)c * (HID / 8) + lane]);
        const __half2* h2 = (const __half2*)&raw;
#pragma unroll
        for (int q = 0; q < 4; q++) {
            float2 f = __half22float2(h2[q]);
            acc[q * 2 + 0] = fmaf(v, f.x, acc[q * 2 + 0]);
            acc[q * 2 + 1] = fmaf(v, f.y, acc[q * 2 + 1]);
        }
    }

    const float4* __restrict__ b4 = (const float4*)bias;
    const float4 bb0 = __ldg(&b4[lane * 2 + 0]);
    const float4 bb1 = __ldg(&b4[lane * 2 + 1]);
#pragma unroll
    for (int q = 0; q < 4; q++) {
        acc[q]     += ((const float*)&bb0)[q];
        acc[q + 4] += ((const float*)&bb1)[q];
    }
    if (RELU) {
#pragma unroll
        for (int j = 0; j < 8; j++) acc[j] = fmaxf(acc[j], 0.f);
    }

    if (OUT_HALF) {
        __half2 h0 = __float22half2_rn(make_float2(acc[0], acc[1]));
        __half2 h1 = __float22half2_rn(make_float2(acc[2], acc[3]));
        __half2 h2 = __float22half2_rn(make_float2(acc[4], acc[5]));
        __half2 h3 = __float22half2_rn(make_float2(acc[6], acc[7]));
        uint4 packed;
        packed.x = *(unsigned*)&h0; packed.y = *(unsigned*)&h1;
        packed.z = *(unsigned*)&h2; packed.w = *(unsigned*)&h3;
        *((uint4*)((__half*)Hout + (size_t)warp * HID) + lane) = packed;
    } else {
        float4* __restrict__ dst = (float4*)((float*)Hout + (size_t)warp * HID);
        dst[lane * 2 + 0] = make_float4(acc[0], acc[1], acc[2], acc[3]);
        dst[lane * 2 + 1] = make_float4(acc[4], acc[5], acc[6], acc[7]);
    }
}

// ---------------------------------------------------------------------------
// Head: per node (one warp): a = relu(L @ fc1W + fc1b); z = a @ fc2W + fc2b;
// out = log_softmax(z). (b2 already folded into spmm2.)
// ---------------------------------------------------------------------------
__global__ __launch_bounds__(256) void head_kernel(
    const float* __restrict__ L,
    const float* __restrict__ fc1W, const float* __restrict__ fc1b,
    const float* __restrict__ fc2W, const float* __restrict__ fc2b,
    float* __restrict__ out, int N)
{
    __shared__ float Wsh[HID * 32];

    const int tid = threadIdx.x;
    for (int i = tid; i < HID * 32; i += blockDim.x) Wsh[i] = fc1W[i];
    __syncthreads();

    const int warp = tid >> 5;
    const int lane = tid & 31;
    const int node = blockIdx.x * (blockDim.x >> 5) + warp;
    if (node >= N) return;

    const float* __restrict__ row = L + (size_t)node * HID;
    float a = fc1b[lane];

#pragma unroll 2
    for (int base = 0; base < HID; base += 32) {
        float xk = row[base + lane];
#pragma unroll
        for (int kk = 0; kk < 32; kk++) {
            float xv = __shfl_sync(0xffffffffu, xk, kk);
            a = fmaf(xv, Wsh[(base + kk) * 32 + lane], a);
        }
    }
    a = fmaxf(a, 0.f);

    float t0 = a * fc2W[lane * 2 + 0];
    float t1 = a * fc2W[lane * 2 + 1];
#pragma unroll
    for (int off = 16; off > 0; off >>= 1) {
        t0 += __shfl_down_sync(0xffffffffu, t0, off);
        t1 += __shfl_down_sync(0xffffffffu, t1, off);
    }
    if (lane == 0) {
        const float z0 = t0 + fc2b[0];
        const float z1 = t1 + fc2b[1];
        const float m = fmaxf(z0, z1);
        const float lse = m + logf(expf(z0 - m) + expf(z1 - m));
        out[node * 2 + 0] = z0 - lse;
        out[node * 2 + 1] = z1 - lse;
    }
}

// ---------------------------------------------------------------------------
extern "C" void kernel_launch(void* const* d_in, const int* in_sizes, int n_in,
                              void* d_out, int out_size)
{
    const float* inputs    = (const float*)d_in[0];
    const int*   edge_rows = (const int*)  d_in[1];
    const int*   edge_cols = (const int*)  d_in[2];
    const float* edge_vals = (const float*)d_in[3];
    const float* W1        = (const float*)d_in[4];
    const float* b1        = (const float*)d_in[5];
    const float* W2        = (const float*)d_in[6];
    const float* b2        = (const float*)d_in[7];
    const float* fc1W      = (const float*)d_in[8];
    const float* fc1b      = (const float*)d_in[9];
    const float* fc2W      = (const float*)d_in[10];
    const float* fc2b      = (const float*)d_in[11];
    float* out = (float*)d_out;

    const int N = in_sizes[0] / IN_DIM;   // 100000
    const int E = in_sizes[1];            // 3200000

    float* bufA; __half* bufS; __half* bufH;
    int* counts; int* rowPtr; int* blockSums; float2* csr;
    cudaGetSymbolAddress((void**)&bufA, g_bufA);
    cudaGetSymbolAddress((void**)&bufS, g_bufS);
    cudaGetSymbolAddress((void**)&bufH, g_bufH);
    cudaGetSymbolAddress((void**)&counts, g_counts);
    cudaGetSymbolAddress((void**)&rowPtr, g_rowPtr);
    cudaGetSymbolAddress((void**)&blockSums, g_blockSums);
    cudaGetSymbolAddress((void**)&csr, g_csr);

    const int nScanBlocks = (N + SCAN_B - 1) / SCAN_B;   // 391

    // ---- CSR build (shared by both SpMMs) ----
    cudaMemsetAsync(counts, 0, (size_t)N * sizeof(int));
    histogram_kernel<<<512, 256>>>(edge_rows, counts, E);
    scan1_kernel<<<nScanBlocks, SCAN_B>>>(counts, rowPtr, blockSums, N);
    scan2_kernel<<<1, 512>>>(blockSums, nScanBlocks);
    scan3_kernel<<<nScanBlocks, SCAN_B>>>(rowPtr, blockSums, counts /*wptr*/, N, E);
    scatter_kernel<<<512, 256>>>(edge_rows, edge_cols, edge_vals, counts, csr, E);

    const int gemmBlocks = (N + BM - 1) / BM;   // grid.x only (BN == HID)
    const int spmmBlocks = (N + 7) / 8;         // 8 warps/block, warp per node

    // ---- Layer 1: S1 = f16(X @ W1); H = f16(relu(spmm(S1) + b1)) ----
    gemm_tc_kernel<float><<<gemmBlocks, 256>>>(inputs, W1, bufS, N, IN_DIM, HID);
    spmm_csr_f16_kernel<true, true><<<spmmBlocks, 256>>>(rowPtr, csr, bufS, b1, bufH, N);

    // ---- Layer 2: S2 = f16(H @ W2); L = spmm(S2) + b2 (fp32) ----
    gemm_tc_kernel<__half><<<gemmBlocks, 256>>>(bufH, W2, bufS, N, HID, HID);
    spmm_csr_f16_kernel<false, false><<<spmmBlocks, 256>>>(rowPtr, csr, bufS, b2, bufA, N);

    // ---- Head + log_softmax ----
    head_kernel<<<(N + 7) / 8, 256>>>(bufA, fc1W, fc1b, fc2W, fc2b, out, N);
}